// round 2
// baseline (speedup 1.0000x reference)
#include <cuda_runtime.h>
#include <cuda_bf16.h>

// actions: [B=4096, T=256, A=64] fp32
// out[b,0,a] = x[b,0,a]
// out[b,t,a] = out[b,t-1,a] + clip(x[b,t,a] - x[b,t-1,a], -0.5, 0.5)
//
// One thread per (b, a-pair) float2 lane: 32 lanes per (b,t) row of 64 floats.
// 131072 threads = 1024 CTAs x 128 -> ~6.9 CTAs/SM (balanced waves, occ ~40%).
// Loads address-independent of the accumulator; unroll keeps 8 loads in flight.

#define TT   256        // time steps
#define ROW2 32         // float2 lanes per row (64 floats / 2)
#define MAXD 0.5f

__global__ __launch_bounds__(128) void smooth_scan_kernel(
    const float2* __restrict__ in, float2* __restrict__ out)
{
    const unsigned idx = blockIdx.x * blockDim.x + threadIdx.x;  // 0..131071
    const unsigned b  = idx >> 5;     // batch
    const unsigned a2 = idx & 31;     // float2 lane within row

    size_t base = (size_t)b * (TT * ROW2) + a2;

    float2 prev = __ldcs(&in[base]);  // raw x[t-1]
    float2 acc  = prev;               // reconstructed out[t-1]
    __stcs(&out[base], acc);

    #pragma unroll 8
    for (int t = 1; t < TT; ++t) {
        float2 x = __ldcs(&in[base + (size_t)t * ROW2]);

        float dx = fminf(fmaxf(x.x - prev.x, -MAXD), MAXD);
        float dy = fminf(fmaxf(x.y - prev.y, -MAXD), MAXD);

        acc.x += dx;
        acc.y += dy;
        prev = x;

        __stcs(&out[base + (size_t)t * ROW2], acc);
    }
}

extern "C" void kernel_launch(void* const* d_in, const int* in_sizes, int n_in,
                              void* d_out, int out_size)
{
    const float2* in  = (const float2*)d_in[0];
    float2*       out = (float2*)d_out;

    // total lanes = B * 32 = 4096 * 32 = 131072
    const int threads = 128;
    const int blocks  = (4096 * ROW2) / threads;  // 1024
    smooth_scan_kernel<<<blocks, threads>>>(in, out);
}

// round 3
// speedup vs baseline: 1.6143x; 1.6143x over previous
#include <cuda_runtime.h>
#include <cuda_bf16.h>

// actions: [B=4096, T=256, A=64] fp32
// out[b,0,a] = x[b,0,a]
// out[b,t,a] = out[b,t-1,a] + clip(x[b,t,a] - x[b,t-1,a], -0.5, 0.5)
//
// One thread per (b, a-quad) float4 lane: 16 lanes per (b,t) row of 64 floats.
// 65536 threads. block=64 -> 1024 CTAs -> 6.92 CTAs/SM: near-perfect wave
// balance (the 512x128 config had a 16% tail from 4-vs-3 CTAs per SM).
// Plain LDG/STG (R2 showed .cs streaming hints regress DRAM% badly).

#define TT   256        // time steps
#define ROW4 16         // float4 lanes per row (64 floats / 4)
#define MAXD 0.5f

__global__ __launch_bounds__(64) void smooth_scan_kernel(
    const float4* __restrict__ in, float4* __restrict__ out)
{
    const unsigned idx = blockIdx.x * blockDim.x + threadIdx.x;  // 0..65535
    const unsigned b  = idx >> 4;     // batch
    const unsigned a4 = idx & 15;     // float4 lane within row

    size_t base = (size_t)b * (TT * ROW4) + a4;

    float4 prev = in[base];   // raw x[t-1]
    float4 acc  = prev;       // reconstructed out[t-1]
    out[base] = acc;

    #pragma unroll 8
    for (int t = 1; t < TT; ++t) {
        float4 x = in[base + (size_t)t * ROW4];

        float dx = fminf(fmaxf(x.x - prev.x, -MAXD), MAXD);
        float dy = fminf(fmaxf(x.y - prev.y, -MAXD), MAXD);
        float dz = fminf(fmaxf(x.z - prev.z, -MAXD), MAXD);
        float dw = fminf(fmaxf(x.w - prev.w, -MAXD), MAXD);

        acc.x += dx; acc.y += dy; acc.z += dz; acc.w += dw;
        prev = x;

        out[base + (size_t)t * ROW4] = acc;
    }
}

extern "C" void kernel_launch(void* const* d_in, const int* in_sizes, int n_in,
                              void* d_out, int out_size)
{
    const float4* in  = (const float4*)d_in[0];
    float4*       out = (float4*)d_out;

    // total lanes = B * 16 = 4096 * 16 = 65536
    const int threads = 64;
    const int blocks  = (4096 * ROW4) / threads;  // 1024
    smooth_scan_kernel<<<blocks, threads>>>(in, out);
}

// round 4
// speedup vs baseline: 1.6962x; 1.0507x over previous
#include <cuda_runtime.h>
#include <cuda_bf16.h>

// actions: [B=4096, T=256, A=64] fp32
// out[b,0,a] = x[b,0,a]
// out[b,t,a] = out[b,t-1,a] + clip(x[b,t,a] - x[b,t-1,a], -0.5, 0.5)
//
// One thread per (b, a-quad) float4 lane: 16 lanes per (b,t) row.
// Grid 512 x 128 (best measured config, R1). Body processes 4 timesteps per
// iteration with all 4 LDG.128 issued before any dependent math/store ->
// forces MLP~4 per thread (~28 KB in-flight per SM) to fill DRAM latency.

#define TT   256
#define ROW4 16
#define MAXD 0.5f

__device__ __forceinline__ void step(float4& acc, float4& prev, const float4 x)
{
    acc.x += fminf(fmaxf(x.x - prev.x, -MAXD), MAXD);
    acc.y += fminf(fmaxf(x.y - prev.y, -MAXD), MAXD);
    acc.z += fminf(fmaxf(x.z - prev.z, -MAXD), MAXD);
    acc.w += fminf(fmaxf(x.w - prev.w, -MAXD), MAXD);
    prev = x;
}

__global__ __launch_bounds__(128) void smooth_scan_kernel(
    const float4* __restrict__ in, float4* __restrict__ out)
{
    const unsigned idx = blockIdx.x * blockDim.x + threadIdx.x;  // 0..65535
    const unsigned b  = idx >> 4;
    const unsigned a4 = idx & 15;

    size_t base = (size_t)b * (TT * ROW4) + a4;

    float4 prev = in[base];
    float4 acc  = prev;
    out[base] = acc;

    // t = 1,2,3 (peel to align main loop on multiples of 4)
    {
        float4 x1 = in[base + 1 * ROW4];
        float4 x2 = in[base + 2 * ROW4];
        float4 x3 = in[base + 3 * ROW4];
        step(acc, prev, x1); out[base + 1 * ROW4] = acc;
        step(acc, prev, x2); out[base + 2 * ROW4] = acc;
        step(acc, prev, x3); out[base + 3 * ROW4] = acc;
    }

    for (int t = 4; t < TT; t += 4) {
        const size_t p = base + (size_t)t * ROW4;
        // Front-batched loads: independent of acc -> 4 LDG.128 in flight.
        float4 x0 = in[p + 0 * ROW4];
        float4 x1 = in[p + 1 * ROW4];
        float4 x2 = in[p + 2 * ROW4];
        float4 x3 = in[p + 3 * ROW4];

        step(acc, prev, x0); out[p + 0 * ROW4] = acc;
        step(acc, prev, x1); out[p + 1 * ROW4] = acc;
        step(acc, prev, x2); out[p + 2 * ROW4] = acc;
        step(acc, prev, x3); out[p + 3 * ROW4] = acc;
    }
}

extern "C" void kernel_launch(void* const* d_in, const int* in_sizes, int n_in,
                              void* d_out, int out_size)
{
    const float4* in  = (const float4*)d_in[0];
    float4*       out = (float4*)d_out;

    const int threads = 128;
    const int blocks  = (4096 * ROW4) / threads;  // 512
    smooth_scan_kernel<<<blocks, threads>>>(in, out);
}